// round 1
// baseline (speedup 1.0000x reference)
#include <cuda_runtime.h>

typedef unsigned long long ULL;

__device__ __forceinline__ ULL ffma2(ULL a, ULL b, ULL c) {
    ULL d;
    asm("fma.rn.f32x2 %0, %1, %2, %3;" : "=l"(d) : "l"(a), "l"(b), "l"(c));
    return d;
}
__device__ __forceinline__ ULL pack2(float lo, float hi) {
    ULL r;
    asm("mov.b64 %0, {%1, %2};" : "=l"(r) : "f"(lo), "f"(hi));
    return r;
}
__device__ __forceinline__ void unpack2(ULL v, float& lo, float& hi) {
    asm("mov.b64 {%0, %1}, %2;" : "=f"(lo), "=f"(hi) : "l"(v));
}

// Scratch for t = x @ projector : [4*1024, 64] fp32 = 1 MB (static, no allocation)
__device__ float g_t[4 * 1024 * 64];

// ---------------------------------------------------------------------------
// Kernel A: t[r, c] = sum_k x[r, k] * p[k, c]
// 4096 rows x 64 cols, K = 1024. Tile: 32 rows x 64 cols per block, K-tile 64.
// Per thread: 2 rows x 4 cols, accumulated as f32x2 pairs.
// ---------------------------------------------------------------------------
__global__ __launch_bounds__(256) void proj_kernel(const float* __restrict__ x,
                                                   const float* __restrict__ p) {
    __shared__ float xs[32][68];   // padded rows (68 floats = 272 B, 16B-aligned)
    __shared__ float ps[64][64];   // projector K-tile, row k contiguous in c

    const int tid = threadIdx.x;
    const int tx = tid & 15;        // col group: cols 4*tx .. 4*tx+3
    const int ty = tid >> 4;        // row group: rows 2*ty, 2*ty+1
    const int r0 = blockIdx.x * 32;

    ULL acc00 = 0, acc01 = 0, acc10 = 0, acc11 = 0;

    for (int k0 = 0; k0 < 1024; k0 += 64) {
        // load x tile: 32 x 64 floats (512 float4, 2 per thread)
        #pragma unroll
        for (int l = 0; l < 2; l++) {
            int idx = tid + 256 * l;
            int row = idx >> 4, q = idx & 15;
            *(float4*)&xs[row][4 * q] =
                *(const float4*)&x[(size_t)(r0 + row) * 1024 + k0 + 4 * q];
        }
        // load projector tile: 64 x 64 floats (1024 float4, 4 per thread)
        #pragma unroll
        for (int l = 0; l < 4; l++) {
            int idx = tid + 256 * l;
            int row = idx >> 4, q = idx & 15;
            *(float4*)&ps[row][4 * q] =
                *(const float4*)&p[(size_t)(k0 + row) * 64 + 4 * q];
        }
        __syncthreads();

        #pragma unroll 16
        for (int k = 0; k < 64; k++) {
            float4 bv = *(float4*)&ps[k][4 * tx];
            ULL b01 = pack2(bv.x, bv.y);
            ULL b23 = pack2(bv.z, bv.w);
            float a0 = xs[2 * ty][k];
            float a1 = xs[2 * ty + 1][k];
            ULL a02 = pack2(a0, a0);
            ULL a12 = pack2(a1, a1);
            acc00 = ffma2(a02, b01, acc00);
            acc01 = ffma2(a02, b23, acc01);
            acc10 = ffma2(a12, b01, acc10);
            acc11 = ffma2(a12, b23, acc11);
        }
        __syncthreads();
    }

    float4 o;
    unpack2(acc00, o.x, o.y); unpack2(acc01, o.z, o.w);
    *(float4*)&g_t[(size_t)(r0 + 2 * ty) * 64 + 4 * tx] = o;
    unpack2(acc10, o.x, o.y); unpack2(acc11, o.z, o.w);
    *(float4*)&g_t[(size_t)(r0 + 2 * ty + 1) * 64 + 4 * tx] = o;
}

// ---------------------------------------------------------------------------
// Kernel B: out[b,i,j] = ||t_i||^2 + ||t_j||^2 - 2 * dot(t_i, t_j)
// 64x64 output tile per block, K = 64 fully resident in smem.
// tjT stored transposed [k][j] so the j-dimension reads are LDS.128.
// Per thread: 4 rows x 4 cols via f32x2 accumulators.
// ---------------------------------------------------------------------------
__global__ __launch_bounds__(256) void dist_kernel(float* __restrict__ out) {
    __shared__ float ti[64][68];    // [i][k]
    __shared__ float tjT[64][68];   // [k][j] (transposed)
    __shared__ float ni[64], nj[64];

    const int tid = threadIdx.x;
    const int tx = tid & 15;        // cols 4*tx .. 4*tx+3
    const int ty = tid >> 4;        // rows 4*ty .. 4*ty+3
    const int b = blockIdx.z;
    const int i0 = blockIdx.y * 64;
    const int j0 = blockIdx.x * 64;
    const float* tb = g_t + (size_t)b * 1024 * 64;

    #pragma unroll
    for (int l = 0; l < 4; l++) {
        int idx = tid + 256 * l;
        int row = idx >> 4, q = idx & 15;
        *(float4*)&ti[row][4 * q] =
            *(const float4*)&tb[(size_t)(i0 + row) * 64 + 4 * q];
        float4 v = *(const float4*)&tb[(size_t)(j0 + row) * 64 + 4 * q];
        tjT[4 * q][row]     = v.x;
        tjT[4 * q + 1][row] = v.y;
        tjT[4 * q + 2][row] = v.z;
        tjT[4 * q + 3][row] = v.w;
    }
    __syncthreads();

    // per-row squared norms (cheap: 64 threads x 64 FMA each side)
    if (tid < 64) {
        float s = 0.f;
        #pragma unroll 16
        for (int k = 0; k < 64; k++) { float a = ti[tid][k]; s += a * a; }
        ni[tid] = s;
    } else if (tid < 128) {
        int j = tid - 64;
        float s = 0.f;
        #pragma unroll 16
        for (int k = 0; k < 64; k++) { float a = tjT[k][j]; s += a * a; }
        nj[j] = s;
    }
    __syncthreads();

    ULL acc[4][2] = {};
    #pragma unroll 16
    for (int k = 0; k < 64; k++) {
        float4 bv = *(float4*)&tjT[k][4 * tx];
        ULL b01 = pack2(bv.x, bv.y);
        ULL b23 = pack2(bv.z, bv.w);
        #pragma unroll
        for (int m = 0; m < 4; m++) {
            float a = ti[4 * ty + m][k];
            ULL a2 = pack2(a, a);
            acc[m][0] = ffma2(a2, b01, acc[m][0]);
            acc[m][1] = ffma2(a2, b23, acc[m][1]);
        }
    }

    float* ob = out + ((size_t)b * 1024 + i0) * 1024 + j0;
    const int gj = j0 + 4 * tx;
    #pragma unroll
    for (int m = 0; m < 4; m++) {
        const int li = 4 * ty + m;
        const int gi = i0 + li;
        float nim = ni[li];
        float d0, d1, d2, d3;
        unpack2(acc[m][0], d0, d1);
        unpack2(acc[m][1], d2, d3);
        float4 r;
        r.x = nim + nj[4 * tx]     - 2.f * d0;
        r.y = nim + nj[4 * tx + 1] - 2.f * d1;
        r.z = nim + nj[4 * tx + 2] - 2.f * d2;
        r.w = nim + nj[4 * tx + 3] - 2.f * d3;
        // exact diagonal: reference value is exactly 0 there
        if (gi == gj)     r.x = 0.f;
        if (gi == gj + 1) r.y = 0.f;
        if (gi == gj + 2) r.z = 0.f;
        if (gi == gj + 3) r.w = 0.f;
        *(float4*)&ob[(size_t)li * 1024 + 4 * tx] = r;
    }
}

extern "C" void kernel_launch(void* const* d_in, const int* in_sizes, int n_in,
                              void* d_out, int out_size) {
    const float* x = (const float*)d_in[0];        // [4, 1024, 1024] fp32
    const float* p = (const float*)d_in[1];        // [1024, 64] fp32
    float* out = (float*)d_out;                    // [4, 1024, 1024] fp32

    proj_kernel<<<128, 256>>>(x, p);
    dist_kernel<<<dim3(16, 16, 4), 256>>>(out);
}

// round 3
// speedup vs baseline: 1.0345x; 1.0345x over previous
#include <cuda_runtime.h>

typedef unsigned long long ULL;

__device__ __forceinline__ ULL ffma2(ULL a, ULL b, ULL c) {
    ULL d;
    asm("fma.rn.f32x2 %0, %1, %2, %3;" : "=l"(d) : "l"(a), "l"(b), "l"(c));
    return d;
}
__device__ __forceinline__ ULL pack2(float lo, float hi) {
    ULL r;
    asm("mov.b64 %0, {%1, %2};" : "=l"(r) : "f"(lo), "f"(hi));
    return r;
}
__device__ __forceinline__ void unpack2(ULL v, float& lo, float& hi) {
    asm("mov.b64 {%0, %1}, %2;" : "=f"(lo), "=f"(hi) : "l"(v));
}

// Scratch (static, no allocation):
// split-K partials of t, stored TRANSPOSED: [ksplit][rank_col][global_row]
__device__ float g_part[2][64][4096];
// reduced t, transposed k-major: [rank_col][global_row]
__device__ float g_tT[64][4096];

// ---------------------------------------------------------------------------
// Kernel A: partial t, split-K=2. Grid (64 row-tiles, 2 ksplits), 256 thr.
// Block: 64 rows x 64 cols over K-half of 512 (8 K-tiles of 64).
// Per thread 4i x 4j; accumulators paired over j (b-pairs are free LDS.128
// from the k-major projector tile). Register-prefetch double buffering.
// ---------------------------------------------------------------------------
__global__ __launch_bounds__(256) void proj_kernel(const float* __restrict__ x,
                                                   const float* __restrict__ p) {
    __shared__ float xs[64][68];   // x tile [i][k], padded
    __shared__ float ps[64][64];   // projector tile [k][j] (k-major, natural)

    const int tid = threadIdx.x;
    const int jg = tid & 15;       // j group: cols 4*jg .. 4*jg+3
    const int ig = tid >> 4;       // i group: rows 4*ig .. 4*ig+3
    const int r0 = blockIdx.x * 64;
    const int ks = blockIdx.y;
    const int k0base = ks * 512;

    ULL acc[4][2] = {};
    float4 xr[4], pr[4];

    const float* xbase = x + (size_t)r0 * 1024 + k0base;

    // prologue: load tile 0 into regs
    #pragma unroll
    for (int l = 0; l < 4; l++) {
        int idx = tid + 256 * l;
        int row = idx >> 4, q = idx & 15;
        xr[l] = *(const float4*)&xbase[(size_t)row * 1024 + 4 * q];
        pr[l] = *(const float4*)&p[(size_t)(k0base + row) * 64 + 4 * q];
    }
    #pragma unroll
    for (int l = 0; l < 4; l++) {
        int idx = tid + 256 * l;
        int row = idx >> 4, q = idx & 15;
        *(float4*)&xs[row][4 * q] = xr[l];
        *(float4*)&ps[row][4 * q] = pr[l];
    }
    __syncthreads();

    #pragma unroll 1
    for (int t = 0; t < 8; t++) {
        if (t < 7) {
            // prefetch next K-tile into registers (overlaps with compute)
            #pragma unroll
            for (int l = 0; l < 4; l++) {
                int idx = tid + 256 * l;
                int row = idx >> 4, q = idx & 15;
                xr[l] = *(const float4*)&xbase[(size_t)row * 1024 + (t + 1) * 64 + 4 * q];
                pr[l] = *(const float4*)&p[(size_t)(k0base + (t + 1) * 64 + row) * 64 + 4 * q];
            }
        }
        #pragma unroll 16
        for (int k = 0; k < 64; k++) {
            ulonglong2 bv = *(const ulonglong2*)&ps[k][4 * jg];
            #pragma unroll
            for (int m = 0; m < 4; m++) {
                float a = xs[4 * ig + m][k];
                ULL A = pack2(a, a);
                acc[m][0] = ffma2(A, bv.x, acc[m][0]);
                acc[m][1] = ffma2(A, bv.y, acc[m][1]);
            }
        }
        __syncthreads();
        if (t < 7) {
            #pragma unroll
            for (int l = 0; l < 4; l++) {
                int idx = tid + 256 * l;
                int row = idx >> 4, q = idx & 15;
                *(float4*)&xs[row][4 * q] = xr[l];
                *(float4*)&ps[row][4 * q] = pr[l];
            }
            __syncthreads();
        }
    }

    // epilogue: stage transposed tile in smem (reuse xs), then coalesced STG
    float* tsT = &xs[0][0];   // [c][i], stride 68
    #pragma unroll
    for (int m = 0; m < 4; m++) {
        #pragma unroll
        for (int jp = 0; jp < 2; jp++) {
            float vlo, vhi;
            unpack2(acc[m][jp], vlo, vhi);
            int i = 4 * ig + m;
            tsT[(4 * jg + 2 * jp) * 68 + i]     = vlo;
            tsT[(4 * jg + 2 * jp + 1) * 68 + i] = vhi;
        }
    }
    __syncthreads();
    #pragma unroll
    for (int l = 0; l < 4; l++) {
        int idx = tid + 256 * l;
        int c = idx >> 4, q = idx & 15;
        *(float4*)&g_part[ks][c][r0 + 4 * q] = *(float4*)&tsT[c * 68 + 4 * q];
    }
}

// ---------------------------------------------------------------------------
// Kernel B: reduce the two K-split partials into g_tT. 64 blocks x 256 thr.
// ---------------------------------------------------------------------------
__global__ __launch_bounds__(256) void reduce_kernel() {
    const float4* A = (const float4*)&g_part[0][0][0];
    const float4* B = (const float4*)&g_part[1][0][0];
    float4* O = (float4*)&g_tT[0][0];
    int base = blockIdx.x * 256 + threadIdx.x;   // 16384 threads, 65536 float4
    #pragma unroll
    for (int l = 0; l < 4; l++) {
        int e = base + l * 16384;
        float4 a = A[e], b = B[e];
        float4 r;
        r.x = a.x + b.x; r.y = a.y + b.y; r.z = a.z + b.z; r.w = a.w + b.w;
        O[e] = r;
    }
}

// ---------------------------------------------------------------------------
// Kernel C: out[b,i,j] = ni + nj - 2*dot(t_i,t_j).
// Block tile 64i x 128j, K=64 fully resident, both tiles k-major from g_tT.
// Per thread 4i x 8j; b-side j-pairs free via LDS.128, a-side broadcast.
// Norms computed in-block from the resident tiles; shared by overwriting tiT.
// ---------------------------------------------------------------------------
__global__ __launch_bounds__(256) void dist_kernel(float* __restrict__ out) {
    __shared__ float tiT[64][64];    // [k][i]
    __shared__ float tjT[64][128];   // [k][j]

    const int tid = threadIdx.x;
    const int jg = tid & 15;         // cols 8*jg .. 8*jg+7
    const int ig = tid >> 4;         // rows 4*ig .. 4*ig+3
    const int b = blockIdx.z;
    const int i0 = blockIdx.y * 64;
    const int j0 = blockIdx.x * 128;

    // load tiles (both k-major, straight vectorized copies)
    #pragma unroll
    for (int l = 0; l < 4; l++) {
        int idx = tid + 256 * l;
        int c = idx >> 4, q = idx & 15;
        *(float4*)&tiT[c][4 * q] = *(const float4*)&g_tT[c][b * 1024 + i0 + 4 * q];
    }
    #pragma unroll
    for (int l = 0; l < 8; l++) {
        int idx = tid + 256 * l;
        int c = idx >> 5, q = idx & 31;
        *(float4*)&tjT[c][4 * q] = *(const float4*)&g_tT[c][b * 1024 + j0 + 4 * q];
    }
    __syncthreads();

    ULL acc[4][4] = {};
    #pragma unroll 16
    for (int k = 0; k < 64; k++) {
        ulonglong2 b01 = *(const ulonglong2*)&tjT[k][8 * jg];
        ulonglong2 b23 = *(const ulonglong2*)&tjT[k][8 * jg + 4];
        #pragma unroll
        for (int m = 0; m < 4; m++) {
            float a = tiT[k][4 * ig + m];
            ULL A = pack2(a, a);
            acc[m][0] = ffma2(A, b01.x, acc[m][0]);
            acc[m][1] = ffma2(A, b01.y, acc[m][1]);
            acc[m][2] = ffma2(A, b23.x, acc[m][2]);
            acc[m][3] = ffma2(A, b23.y, acc[m][3]);
        }
    }

    // norms from the resident tiles
    float nval = 0.f;
    if (tid < 64) {
        #pragma unroll 16
        for (int k = 0; k < 64; k++) { float v = tiT[k][tid]; nval += v * v; }
    } else if (tid < 192) {
        int j = tid - 64;
        #pragma unroll 16
        for (int k = 0; k < 64; k++) { float v = tjT[k][j]; nval += v * v; }
    }
    __syncthreads();                 // all k-loop / norm reads done
    float* nbuf = &tiT[0][0];        // overwrite tiT: [0..63]=ni, [64..191]=nj
    if (tid < 192) nbuf[tid] = nval;
    __syncthreads();

    // epilogue
    float nj8[8];
    #pragma unroll
    for (int jj = 0; jj < 8; jj++) nj8[jj] = nbuf[64 + 8 * jg + jj];

    #pragma unroll
    for (int m = 0; m < 4; m++) {
        const int li = 4 * ig + m;
        const float nim = nbuf[li];
        float d[8];
        unpack2(acc[m][0], d[0], d[1]);
        unpack2(acc[m][1], d[2], d[3]);
        unpack2(acc[m][2], d[4], d[5]);
        unpack2(acc[m][3], d[6], d[7]);
        float r[8];
        #pragma unroll
        for (int jj = 0; jj < 8; jj++) {
            r[jj] = nim + nj8[jj] - 2.f * d[jj];
            if (i0 + li == j0 + 8 * jg + jj) r[jj] = 0.f;   // exact diagonal
        }
        float* ob = out + ((size_t)b * 1024 + i0 + li) * 1024 + j0 + 8 * jg;
        float4 v0 = {r[0], r[1], r[2], r[3]};
        float4 v1 = {r[4], r[5], r[6], r[7]};
        *(float4*)&ob[0] = v0;
        *(float4*)&ob[4] = v1;
    }
}

extern "C" void kernel_launch(void* const* d_in, const int* in_sizes, int n_in,
                              void* d_out, int out_size) {
    const float* x = (const float*)d_in[0];   // [4, 1024, 1024] fp32
    const float* p = (const float*)d_in[1];   // [1024, 64] fp32
    float* out = (float*)d_out;               // [4, 1024, 1024] fp32

    proj_kernel<<<dim3(64, 2), 256>>>(x, p);
    reduce_kernel<<<64, 256>>>();
    dist_kernel<<<dim3(8, 16, 4), 256>>>(out);
}

// round 9
// speedup vs baseline: 1.7231x; 1.6656x over previous
#include <cuda_runtime.h>
#include <cuda_bf16.h>
#include <cstdint>

// ============================ helpers ============================
__device__ __forceinline__ uint32_t smem_u32(const void* p) {
    uint32_t a;
    asm("{ .reg .u64 t; cvta.to.shared.u64 t, %1; cvt.u32.u64 %0, t; }"
        : "=r"(a) : "l"(p));
    return a;
}

__device__ __forceinline__ void ldsm_x4(uint32_t* r, uint32_t addr) {
    asm volatile("ldmatrix.sync.aligned.m8n8.x4.shared.b16 {%0,%1,%2,%3}, [%4];"
                 : "=r"(r[0]), "=r"(r[1]), "=r"(r[2]), "=r"(r[3]) : "r"(addr));
}

__device__ __forceinline__ void mma_bf16(float* c, const uint32_t* a, const uint32_t* b) {
    asm volatile(
        "mma.sync.aligned.m16n8k16.row.col.f32.bf16.bf16.f32 "
        "{%0,%1,%2,%3}, {%4,%5,%6,%7}, {%8,%9}, {%0,%1,%2,%3};"
        : "+f"(c[0]), "+f"(c[1]), "+f"(c[2]), "+f"(c[3])
        : "r"(a[0]), "r"(a[1]), "r"(a[2]), "r"(a[3]), "r"(b[0]), "r"(b[1]));
}

// fp32 -> bf16 hi + bf16 lo (residual)
__device__ __forceinline__ void f2hl(float v, unsigned short& h, unsigned short& l) {
    __nv_bfloat16 hb = __float2bfloat16(v);
    float r = v - __bfloat162float(hb);
    h = __bfloat16_as_ushort(hb);
    l = __bfloat16_as_ushort(__float2bfloat16(r));
}

// ============================ global scratch ============================
__device__ __align__(16) float g_part[4][4096][64];        // split-K partials (4 MB)
__device__ __align__(16) __nv_bfloat16 g_thi[4096 * 64];   // t hi
__device__ __align__(16) __nv_bfloat16 g_tlo[4096 * 64];   // t lo
__device__ float g_norm[4096];                             // row norms

// padded row stride (halves): 72 -> 144 B, conflict-free ldmatrix
#define RS 72
#define RSB 144

// proj smem (bytes)
#define PA_HI 0
#define PA_LO 18432
#define PB_HI 36864
#define PB_LO 46080
#define P_SMEM 55296

// dist smem (bytes)
#define DA_HI 0
#define DA_LO 18432
#define DB_HI 36864
#define DB_LO 55296
#define D_NI  73728
#define D_NJ  74240
#define D_SMEM 74752

// ---------------------------------------------------------------------------
// Kernel 1: proj. grid (32 M-tiles, 4 K-splits) x 256 thr.
// t_part[128 x 64] = x[128 x 256] @ p[256 x 64], bf16 hi/lo 3-pass mma.sync.
// Warp tile 32m x 32n (8 warps as 4x2).
// ---------------------------------------------------------------------------
__global__ __launch_bounds__(256) void proj_mma(const float* __restrict__ x,
                                                const float* __restrict__ p) {
    extern __shared__ __align__(16) unsigned char sm[];
    const uint32_t sb = smem_u32(sm);
    const int tid = threadIdx.x, lane = tid & 31, wid = tid >> 5;
    const int r0 = blockIdx.x * 128;
    const int kbase = blockIdx.y * 256;
    const int wm = wid & 3, wn = wid >> 2;

    float acc[2][4][4];
    #pragma unroll
    for (int i = 0; i < 2; i++)
        #pragma unroll
        for (int j = 0; j < 4; j++)
            #pragma unroll
            for (int q = 0; q < 4; q++) acc[i][j][q] = 0.f;

    const uint32_t aoff[3] = {PA_HI, PA_HI, PA_LO};
    const uint32_t boff[3] = {PB_HI, PB_LO, PB_HI};

    #pragma unroll 1
    for (int ct = 0; ct < 4; ct++) {
        const int k0g = kbase + ct * 64;
        // stage x [128 rows x 64 k] fp32 -> hi/lo bf16, padded rows
        #pragma unroll
        for (int it = 0; it < 8; it++) {
            int idx = tid + 256 * it;
            int row = idx >> 4, q = idx & 15;
            float4 v = *(const float4*)&x[(size_t)(r0 + row) * 1024 + k0g + 4 * q];
            unsigned short h0, h1, h2, h3, l0, l1, l2, l3;
            f2hl(v.x, h0, l0); f2hl(v.y, h1, l1);
            f2hl(v.z, h2, l2); f2hl(v.w, h3, l3);
            uint2 hw, lw;
            hw.x = (uint32_t)h0 | ((uint32_t)h1 << 16);
            hw.y = (uint32_t)h2 | ((uint32_t)h3 << 16);
            lw.x = (uint32_t)l0 | ((uint32_t)l1 << 16);
            lw.y = (uint32_t)l2 | ((uint32_t)l3 << 16);
            uint32_t off = (uint32_t)(row * RS + 4 * q) * 2;
            *(uint2*)(sm + PA_HI + off) = hw;
            *(uint2*)(sm + PA_LO + off) = lw;
        }
        // stage p [64 k x 64 j] -> B[j][k] hi/lo (transpose)
        #pragma unroll
        for (int it = 0; it < 16; it++) {
            int e = tid + 256 * it;
            int kk = e >> 6, j = e & 63;
            float v = p[(size_t)(k0g + kk) * 64 + j];
            unsigned short h, l;
            f2hl(v, h, l);
            uint32_t off = (uint32_t)(j * RS + kk) * 2;
            *(unsigned short*)(sm + PB_HI + off) = h;
            *(unsigned short*)(sm + PB_LO + off) = l;
        }
        __syncthreads();

        #pragma unroll
        for (int ps = 0; ps < 3; ps++) {
            uint32_t abase = sb + aoff[ps] +
                (uint32_t)(wm * 32 + (lane & 15)) * RSB + (uint32_t)(lane >> 4) * 16;
            uint32_t bbase = sb + boff[ps] +
                (uint32_t)(wn * 32 + ((lane >> 4) << 3) + (lane & 7)) * RSB +
                (uint32_t)((lane >> 3) & 1) * 16;
            #pragma unroll
            for (int ks = 0; ks < 4; ks++) {
                uint32_t a0[4], a1[4], b0[4], b1[4];
                ldsm_x4(a0, abase + ks * 32);
                ldsm_x4(a1, abase + 16 * RSB + ks * 32);
                ldsm_x4(b0, bbase + ks * 32);
                ldsm_x4(b1, bbase + 16 * RSB + ks * 32);
                mma_bf16(acc[0][0], a0, b0);
                mma_bf16(acc[0][1], a0, b0 + 2);
                mma_bf16(acc[0][2], a0, b1);
                mma_bf16(acc[0][3], a0, b1 + 2);
                mma_bf16(acc[1][0], a1, b0);
                mma_bf16(acc[1][1], a1, b0 + 2);
                mma_bf16(acc[1][2], a1, b1);
                mma_bf16(acc[1][3], a1, b1 + 2);
            }
        }
        __syncthreads();
    }

    // epilogue: write fp32 partials
    const int ks = blockIdx.y;
    #pragma unroll
    for (int mi = 0; mi < 2; mi++) {
        int rowa = r0 + wm * 32 + mi * 16 + (lane >> 2);
        #pragma unroll
        for (int nt = 0; nt < 4; nt++) {
            int col = wn * 32 + nt * 8 + (lane & 3) * 2;
            float2 v0 = {acc[mi][nt][0], acc[mi][nt][1]};
            float2 v1 = {acc[mi][nt][2], acc[mi][nt][3]};
            *(float2*)&g_part[ks][rowa][col] = v0;
            *(float2*)&g_part[ks][rowa + 8][col] = v1;
        }
    }
}

// ---------------------------------------------------------------------------
// Kernel 2: reduce 4 partials -> norms + bf16 hi/lo. grid 32 x 128.
// ---------------------------------------------------------------------------
__global__ __launch_bounds__(128) void convert_t() {
    int row = blockIdx.x * 128 + threadIdx.x;
    float t[64];
    #pragma unroll
    for (int q = 0; q < 16; q++) {
        float4 a = *(const float4*)&g_part[0][row][4 * q];
        float4 b = *(const float4*)&g_part[1][row][4 * q];
        float4 c = *(const float4*)&g_part[2][row][4 * q];
        float4 d = *(const float4*)&g_part[3][row][4 * q];
        t[4 * q]     = a.x + b.x + c.x + d.x;
        t[4 * q + 1] = a.y + b.y + c.y + d.y;
        t[4 * q + 2] = a.z + b.z + c.z + d.z;
        t[4 * q + 3] = a.w + b.w + c.w + d.w;
    }
    float nm = 0.f;
    #pragma unroll
    for (int k = 0; k < 64; k++) nm += t[k] * t[k];
    g_norm[row] = nm;
    #pragma unroll
    for (int q = 0; q < 16; q++) {
        unsigned short h0, h1, h2, h3, l0, l1, l2, l3;
        f2hl(t[4 * q], h0, l0);     f2hl(t[4 * q + 1], h1, l1);
        f2hl(t[4 * q + 2], h2, l2); f2hl(t[4 * q + 3], h3, l3);
        uint2 hw, lw;
        hw.x = (uint32_t)h0 | ((uint32_t)h1 << 16);
        hw.y = (uint32_t)h2 | ((uint32_t)h3 << 16);
        lw.x = (uint32_t)l0 | ((uint32_t)l1 << 16);
        lw.y = (uint32_t)l2 | ((uint32_t)l3 << 16);
        *(uint2*)&g_thi[(size_t)row * 64 + 4 * q] = hw;
        *(uint2*)&g_tlo[(size_t)row * 64 + 4 * q] = lw;
    }
}

// ---------------------------------------------------------------------------
// Kernel 3: dist. grid (8 j, 8 i, 4 b) x 256 thr. Block 128i x 128j, K=64.
// G via 3-pass bf16 mma.sync; out = ni + nj - 2G fused in the epilogue.
// Warp tile 32m x 64n (8 warps as 4x2).
// ---------------------------------------------------------------------------
__global__ __launch_bounds__(256) void dist_mma(float* __restrict__ out) {
    extern __shared__ __align__(16) unsigned char sm[];
    const uint32_t sb = smem_u32(sm);
    const int tid = threadIdx.x, lane = tid & 31, wid = tid >> 5;
    const int b = blockIdx.z;
    const int i0 = blockIdx.y * 128;
    const int j0 = blockIdx.x * 128;
    const int wm = wid & 3, wn = wid >> 2;

    // stage tiles: A = rows i0..i0+127, B = rows j0..j0+127 (both [row][k])
    const __nv_bfloat16* sih = g_thi + (size_t)(b * 1024 + i0) * 64;
    const __nv_bfloat16* sil = g_tlo + (size_t)(b * 1024 + i0) * 64;
    const __nv_bfloat16* sjh = g_thi + (size_t)(b * 1024 + j0) * 64;
    const __nv_bfloat16* sjl = g_tlo + (size_t)(b * 1024 + j0) * 64;
    #pragma unroll
    for (int it = 0; it < 4; it++) {
        int idx = tid + 256 * it;
        int row = idx >> 3, q = idx & 7;
        uint32_t off = (uint32_t)row * RSB + (uint32_t)q * 16;
        size_t e = (size_t)row * 64 + q * 8;
        *(uint4*)(sm + DA_HI + off) = *(const uint4*)(sih + e);
        *(uint4*)(sm + DA_LO + off) = *(const uint4*)(sil + e);
        *(uint4*)(sm + DB_HI + off) = *(const uint4*)(sjh + e);
        *(uint4*)(sm + DB_LO + off) = *(const uint4*)(sjl + e);
    }
    if (tid < 128)
        ((float*)(sm + D_NI))[tid] = g_norm[b * 1024 + i0 + tid];
    else
        ((float*)(sm + D_NJ))[tid - 128] = g_norm[b * 1024 + j0 + tid - 128];
    __syncthreads();

    float acc[2][8][4];
    #pragma unroll
    for (int i = 0; i < 2; i++)
        #pragma unroll
        for (int j = 0; j < 8; j++)
            #pragma unroll
            for (int q = 0; q < 4; q++) acc[i][j][q] = 0.f;

    const uint32_t aoff[3] = {DA_HI, DA_HI, DA_LO};
    const uint32_t boff[3] = {DB_HI, DB_LO, DB_HI};

    #pragma unroll
    for (int ps = 0; ps < 3; ps++) {
        uint32_t abase = sb + aoff[ps] +
            (uint32_t)(wm * 32 + (lane & 15)) * RSB + (uint32_t)(lane >> 4) * 16;
        uint32_t bbase = sb + boff[ps] +
            (uint32_t)(wn * 64 + ((lane >> 4) << 3) + (lane & 7)) * RSB +
            (uint32_t)((lane >> 3) & 1) * 16;
        #pragma unroll
        for (int ks = 0; ks < 4; ks++) {
            uint32_t a0[4], a1[4];
            ldsm_x4(a0, abase + ks * 32);
            ldsm_x4(a1, abase + 16 * RSB + ks * 32);
            #pragma unroll
            for (int np = 0; np < 4; np++) {
                uint32_t bf[4];
                ldsm_x4(bf, bbase + np * 16 * RSB + ks * 32);
                mma_bf16(acc[0][2 * np], a0, bf);
                mma_bf16(acc[0][2 * np + 1], a0, bf + 2);
                mma_bf16(acc[1][2 * np], a1, bf);
                mma_bf16(acc[1][2 * np + 1], a1, bf + 2);
            }
        }
    }

    // epilogue: out = ni + nj - 2G, exact-0 diagonal
    const float* ni_s = (const float*)(sm + D_NI);
    const float* nj_s = (const float*)(sm + D_NJ);
    const bool diag = (i0 == j0);
    #pragma unroll
    for (int mi = 0; mi < 2; mi++) {
        int lr0 = wm * 32 + mi * 16 + (lane >> 2);
        int lr1 = lr0 + 8;
        float n0 = ni_s[lr0], n1 = ni_s[lr1];
        float* ob0 = out + ((size_t)(b * 1024 + i0 + lr0)) * 1024 + j0;
        float* ob1 = out + ((size_t)(b * 1024 + i0 + lr1)) * 1024 + j0;
        #pragma unroll
        for (int nt = 0; nt < 8; nt++) {
            int lc = wn * 64 + nt * 8 + (lane & 3) * 2;
            float njA = nj_s[lc], njB = nj_s[lc + 1];
            float2 v0, v1;
            v0.x = n0 + njA - 2.f * acc[mi][nt][0];
            v0.y = n0 + njB - 2.f * acc[mi][nt][1];
            v1.x = n1 + njA - 2.f * acc[mi][nt][2];
            v1.y = n1 + njB - 2.f * acc[mi][nt][3];
            if (diag) {
                if (lr0 == lc)     v0.x = 0.f;
                if (lr0 == lc + 1) v0.y = 0.f;
                if (lr1 == lc)     v1.x = 0.f;
                if (lr1 == lc + 1) v1.y = 0.f;
            }
            *(float2*)&ob0[lc] = v0;
            *(float2*)&ob1[lc] = v1;
        }
    }
}

// ============================ launch ============================
extern "C" void kernel_launch(void* const* d_in, const int* in_sizes, int n_in,
                              void* d_out, int out_size) {
    const float* x = (const float*)d_in[0];   // [4, 1024, 1024] fp32
    const float* p = (const float*)d_in[1];   // [1024, 64] fp32
    float* out = (float*)d_out;               // [4, 1024, 1024] fp32

    static bool attr_done = false;
    if (!attr_done) {
        cudaFuncSetAttribute(proj_mma, cudaFuncAttributeMaxDynamicSharedMemorySize, P_SMEM);
        cudaFuncSetAttribute(dist_mma, cudaFuncAttributeMaxDynamicSharedMemorySize, D_SMEM);
        attr_done = true;
    }

    proj_mma<<<dim3(32, 4), 256, P_SMEM>>>(x, p);
    convert_t<<<32, 128>>>();
    dist_mma<<<dim3(8, 8, 4), 256, D_SMEM>>>(out);
}